// round 1
// baseline (speedup 1.0000x reference)
#include <cuda_runtime.h>
#include <math.h>

#define Bv 16
#define Tv 600
#define Hv 512
#define Mv (Bv*Tv)          // 9600 rows
#define G4 (4*Hv)           // 2048 gate rows

// ---------------- scratch (device globals; no allocation) ----------------
__device__ float g_xt [Mv*Hv];        // x transposed [B*T, 512]
__device__ float g_xpf[Mv*G4];        // input-proj fwd  [B*T, 2048]
__device__ float g_xpb[Mv*G4];        // input-proj bwd
__device__ float g_h0 [Mv*2*Hv];      // layer0 output concat [B*T, 1024]
__device__ float g_h1 [Mv*2*Hv];      // layer1 output concat
__device__ float g_fc [Mv*Hv];        // fc output pre-LN
__device__ unsigned g_bar;            // inter-CTA step barrier counter

// ---------------- transpose x[B,H,T] -> g_xt[(b*T+t)*H + h] ----------------
__global__ void k_transpose(const float* __restrict__ x)
{
    __shared__ float tile[32][33];
    int bb = blockIdx.z;
    int t0 = blockIdx.x * 32, h0 = blockIdx.y * 32;
    int tx = threadIdx.x, ty = threadIdx.y;
    #pragma unroll
    for (int i = 0; i < 4; i++) {
        int hh = h0 + ty + i*8;
        int tt = t0 + tx;
        if (tt < Tv) tile[ty + i*8][tx] = x[(bb*Hv + hh)*Tv + tt];
    }
    __syncthreads();
    #pragma unroll
    for (int i = 0; i < 4; i++) {
        int tt = t0 + ty + i*8;
        int hh = h0 + tx;
        if (tt < Tv) g_xt[(bb*Tv + tt)*Hv + hh] = tile[tx][ty + i*8];
    }
}

// ---------------- C[M,N] = A[M,K] @ W[N,K]^T + bias[N] ----------------
// BM=BN=64, BK=16, 256 threads, 4x4 per thread. All dims divide evenly.
__global__ __launch_bounds__(256) void k_gemm(const float* __restrict__ A,
                                              const float* __restrict__ W,
                                              const float* __restrict__ bias,
                                              float* __restrict__ C,
                                              int K, int N)
{
    __shared__ __align__(16) float As[16][68];
    __shared__ __align__(16) float Ws[16][68];
    const int tid = threadIdx.x;
    const int tx = tid & 15, ty = tid >> 4;
    const int m0 = blockIdx.y * 64, n0 = blockIdx.x * 64;
    const int lrow = tid >> 2;            // 0..63
    const int lk   = (tid & 3) * 4;       // 0,4,8,12
    const float* Ap = A + (size_t)(m0 + lrow) * K + lk;
    const float* Wp = W + (size_t)(n0 + lrow) * K + lk;

    float acc[4][4] = {};
    for (int kb = 0; kb < K; kb += 16) {
        float4 va = *(const float4*)(Ap + kb);
        float4 vw = *(const float4*)(Wp + kb);
        As[lk+0][lrow] = va.x; As[lk+1][lrow] = va.y;
        As[lk+2][lrow] = va.z; As[lk+3][lrow] = va.w;
        Ws[lk+0][lrow] = vw.x; Ws[lk+1][lrow] = vw.y;
        Ws[lk+2][lrow] = vw.z; Ws[lk+3][lrow] = vw.w;
        __syncthreads();
        #pragma unroll
        for (int k = 0; k < 16; k++) {
            float4 a = *(const float4*)&As[k][ty*4];
            float4 w = *(const float4*)&Ws[k][tx*4];
            acc[0][0] = fmaf(a.x, w.x, acc[0][0]);
            acc[0][1] = fmaf(a.x, w.y, acc[0][1]);
            acc[0][2] = fmaf(a.x, w.z, acc[0][2]);
            acc[0][3] = fmaf(a.x, w.w, acc[0][3]);
            acc[1][0] = fmaf(a.y, w.x, acc[1][0]);
            acc[1][1] = fmaf(a.y, w.y, acc[1][1]);
            acc[1][2] = fmaf(a.y, w.z, acc[1][2]);
            acc[1][3] = fmaf(a.y, w.w, acc[1][3]);
            acc[2][0] = fmaf(a.z, w.x, acc[2][0]);
            acc[2][1] = fmaf(a.z, w.y, acc[2][1]);
            acc[2][2] = fmaf(a.z, w.z, acc[2][2]);
            acc[2][3] = fmaf(a.z, w.w, acc[2][3]);
            acc[3][0] = fmaf(a.w, w.x, acc[3][0]);
            acc[3][1] = fmaf(a.w, w.y, acc[3][1]);
            acc[3][2] = fmaf(a.w, w.z, acc[3][2]);
            acc[3][3] = fmaf(a.w, w.w, acc[3][3]);
        }
        __syncthreads();
    }
    float4 bv = *(const float4*)&bias[n0 + tx*4];
    #pragma unroll
    for (int i = 0; i < 4; i++) {
        float4 o;
        o.x = acc[i][0] + bv.x; o.y = acc[i][1] + bv.y;
        o.z = acc[i][2] + bv.z; o.w = acc[i][3] + bv.w;
        *(float4*)&C[(size_t)(m0 + ty*4 + i) * N + n0 + tx*4] = o;
    }
}

// ---------------- barrier reset ----------------
__global__ void k_reset() { g_bar = 0u; }

// ---------------- persistent bidirectional LSTM layer ----------------
// 128 blocks: blocks [0,64) forward, [64,128) backward. Block owns 8 hidden
// units (32 gate rows). w_hh slice in SMEM; c state in SMEM; grid barrier / step.
__global__ __launch_bounds__(256, 1) void k_lstm(const float* __restrict__ xpf,
                                                 const float* __restrict__ xpb,
                                                 const float* __restrict__ whhf,
                                                 const float* __restrict__ whhb,
                                                 float* __restrict__ hout)
{
    extern __shared__ float sm[];
    float* w_s  = sm;                 // [32][516]
    float* h_s  = w_s + 32*516;       // [16][516]
    float* xp_s = h_s + 16*516;       // [32][16]
    float* g_s  = xp_s + 512;         // [32][16]
    float* c_s  = g_s + 512;          // [128]  (j*16+b)

    const int tid   = threadIdx.x;
    const int dir   = blockIdx.x >> 6;
    const int slice = blockIdx.x & 63;
    const int u0    = slice * 8;
    const float* xp  = dir ? xpb  : xpf;
    const float* whh = dir ? whhb : whhf;

    // stage w_hh slice: 32 rows x 512 (rows: gate*512 + u0 + j)
    for (int idx = tid; idx < 32*128; idx += 256) {
        int lr = idx >> 7, k4 = (idx & 127) * 4;
        int gr = (lr >> 3) * 512 + u0 + (lr & 7);
        float4 v = *(const float4*)&whh[(size_t)gr * 512 + k4];
        *(float4*)&w_s[lr*516 + k4] = v;
    }
    if (tid < 128) c_s[tid] = 0.f;

    const int lane = tid & 31;
    const int wi   = tid >> 5;
    const int b    = lane & 15;
    const int lr0  = wi*4 + (lane >> 4)*2;
    const int lr1  = lr0 + 1;
    const float* wr0 = w_s + lr0*516;
    const float* wr1 = w_s + lr1*516;
    const float* hr  = h_s + b*516;

    for (int s = 0; s < Tv; s++) {
        int t = dir ? (Tv-1 - s) : s;
        if (s == 0) {
            for (int idx = tid; idx < 16*516; idx += 256) h_s[idx] = 0.f;
        } else {
            int tp = dir ? t + 1 : t - 1;
            for (int idx = tid; idx < 2048; idx += 256) {
                int bb = idx >> 7, k4 = (idx & 127) * 4;
                *(float4*)&h_s[bb*516 + k4] =
                    *(const float4*)&hout[(size_t)(bb*Tv + tp)*1024 + dir*512 + k4];
            }
        }
        // stage xp slice for (all b, our 32 gate rows) at time t
        for (int idx = tid; idx < 512; idx += 256) {
            int j = idx & 7, seg = idx >> 3;
            int bb = seg & 15, gate = seg >> 4;
            xp_s[(gate*8 + j)*16 + bb] =
                xp[(size_t)(bb*Tv + t)*2048 + gate*512 + u0 + j];
        }
        __syncthreads();

        // 2 dot products of length 512 per thread (batch b, rows lr0/lr1)
        float a0 = 0.f, a1 = 0.f;
        #pragma unroll 4
        for (int k = 0; k < 512; k += 4) {
            float4 hv = *(const float4*)&hr[k];
            float4 w0 = *(const float4*)&wr0[k];
            float4 w1 = *(const float4*)&wr1[k];
            a0 = fmaf(hv.x,w0.x, fmaf(hv.y,w0.y, fmaf(hv.z,w0.z, fmaf(hv.w,w0.w, a0))));
            a1 = fmaf(hv.x,w1.x, fmaf(hv.y,w1.y, fmaf(hv.z,w1.z, fmaf(hv.w,w1.w, a1))));
        }
        g_s[lr0*16 + b] = a0 + xp_s[lr0*16 + b];
        g_s[lr1*16 + b] = a1 + xp_s[lr1*16 + b];
        __syncthreads();

        if (tid < 128) {
            int bb = tid & 15, j = tid >> 4;
            float gi = g_s[( 0 + j)*16 + bb];
            float gf = g_s[( 8 + j)*16 + bb];
            float gg = g_s[(16 + j)*16 + bb];
            float go = g_s[(24 + j)*16 + bb];
            float iv = 1.f / (1.f + expf(-gi));
            float fv = 1.f / (1.f + expf(-gf));
            float gv = tanhf(gg);
            float ov = 1.f / (1.f + expf(-go));
            float c  = fv * c_s[tid] + iv * gv;
            c_s[tid] = c;
            hout[(size_t)(bb*Tv + t)*1024 + dir*512 + u0 + j] = ov * tanhf(c);
        }
        // grid barrier (cumulative counter; 128 co-resident blocks)
        __threadfence();
        __syncthreads();
        if (tid == 0) {
            atomicAdd(&g_bar, 1u);
            unsigned target = 128u * (unsigned)(s + 1);
            while (*(volatile unsigned*)&g_bar < target) { }
            __threadfence();
        }
        __syncthreads();
    }
}

// ---------------- LayerNorm + ReLU (warp per row of 512) ----------------
__global__ __launch_bounds__(256) void k_lnrelu(const float* __restrict__ in,
                                                const float* __restrict__ lnw,
                                                const float* __restrict__ lnb,
                                                float* __restrict__ out)
{
    int row  = blockIdx.x * 8 + (threadIdx.x >> 5);
    int lane = threadIdx.x & 31;
    const float* p = in + (size_t)row * 512;
    float4 v[4];
    float s = 0.f, s2 = 0.f;
    #pragma unroll
    for (int i = 0; i < 4; i++) {
        v[i] = *(const float4*)&p[i*128 + lane*4];
        s  += v[i].x + v[i].y + v[i].z + v[i].w;
        s2 += v[i].x*v[i].x + v[i].y*v[i].y + v[i].z*v[i].z + v[i].w*v[i].w;
    }
    #pragma unroll
    for (int o = 16; o; o >>= 1) {
        s  += __shfl_xor_sync(0xffffffffu, s,  o);
        s2 += __shfl_xor_sync(0xffffffffu, s2, o);
    }
    float mu   = s * (1.f/512.f);
    float var  = s2 * (1.f/512.f) - mu*mu;
    float rstd = rsqrtf(var + 1e-5f);
    float* q = out + (size_t)row * 512;
    #pragma unroll
    for (int i = 0; i < 4; i++) {
        int k = i*128 + lane*4;
        float4 wv = *(const float4*)&lnw[k];
        float4 bv = *(const float4*)&lnb[k];
        float4 o4;
        o4.x = fmaxf((v[i].x - mu)*rstd*wv.x + bv.x, 0.f);
        o4.y = fmaxf((v[i].y - mu)*rstd*wv.y + bv.y, 0.f);
        o4.z = fmaxf((v[i].z - mu)*rstd*wv.z + bv.z, 0.f);
        o4.w = fmaxf((v[i].w - mu)*rstd*wv.w + bv.w, 0.f);
        *(float4*)&q[k] = o4;
    }
}

// ---------------- host ----------------
extern "C" void kernel_launch(void* const* d_in, const int* in_sizes, int n_in,
                              void* d_out, int out_size)
{
    const float* x       = (const float*)d_in[0];
    const float* wih_l0f = (const float*)d_in[1];
    const float* whh_l0f = (const float*)d_in[2];
    const float* b_l0f   = (const float*)d_in[3];
    const float* wih_l0b = (const float*)d_in[4];
    const float* whh_l0b = (const float*)d_in[5];
    const float* b_l0b   = (const float*)d_in[6];
    const float* wih_l1f = (const float*)d_in[7];
    const float* whh_l1f = (const float*)d_in[8];
    const float* b_l1f   = (const float*)d_in[9];
    const float* wih_l1b = (const float*)d_in[10];
    const float* whh_l1b = (const float*)d_in[11];
    const float* b_l1b   = (const float*)d_in[12];
    const float* fc_w    = (const float*)d_in[13];
    const float* fc_b    = (const float*)d_in[14];
    const float* ln_w    = (const float*)d_in[15];
    const float* ln_b    = (const float*)d_in[16];
    float* out = (float*)d_out;

    void *p_xt, *p_xpf, *p_xpb, *p_h0, *p_h1, *p_fc;
    cudaGetSymbolAddress(&p_xt,  g_xt);
    cudaGetSymbolAddress(&p_xpf, g_xpf);
    cudaGetSymbolAddress(&p_xpb, g_xpb);
    cudaGetSymbolAddress(&p_h0,  g_h0);
    cudaGetSymbolAddress(&p_h1,  g_h1);
    cudaGetSymbolAddress(&p_fc,  g_fc);

    const size_t LSTM_SMEM = (32*516 + 16*516 + 512 + 512 + 128) * sizeof(float); // 103680 B
    cudaFuncSetAttribute(k_lstm, cudaFuncAttributeMaxDynamicSharedMemorySize, (int)LSTM_SMEM);

    // transpose input
    k_transpose<<<dim3(19, 16, 16), dim3(32, 8)>>>(x);

    // layer 0 input projections
    k_gemm<<<dim3(32, 150), 256>>>((const float*)p_xt, wih_l0f, b_l0f, (float*)p_xpf, 512, 2048);
    k_gemm<<<dim3(32, 150), 256>>>((const float*)p_xt, wih_l0b, b_l0b, (float*)p_xpb, 512, 2048);
    // layer 0 recurrence
    k_reset<<<1, 1>>>();
    k_lstm<<<128, 256, LSTM_SMEM>>>((const float*)p_xpf, (const float*)p_xpb,
                                    whh_l0f, whh_l0b, (float*)p_h0);
    // layer 1 input projections (K = 1024)
    k_gemm<<<dim3(32, 150), 256>>>((const float*)p_h0, wih_l1f, b_l1f, (float*)p_xpf, 1024, 2048);
    k_gemm<<<dim3(32, 150), 256>>>((const float*)p_h0, wih_l1b, b_l1b, (float*)p_xpb, 1024, 2048);
    // layer 1 recurrence
    k_reset<<<1, 1>>>();
    k_lstm<<<128, 256, LSTM_SMEM>>>((const float*)p_xpf, (const float*)p_xpb,
                                    whh_l1f, whh_l1b, (float*)p_h1);
    // fc + layernorm + relu
    k_gemm<<<dim3(8, 150), 256>>>((const float*)p_h1, fc_w, fc_b, (float*)p_fc, 1024, 512);
    k_lnrelu<<<1200, 256>>>((const float*)p_fc, ln_w, ln_b, out);
}